// round 9
// baseline (speedup 1.0000x reference)
#include <cuda_runtime.h>
#include <cuda_bf16.h>
#include <math.h>

// DynamicRouter: logits = x @ W^T + b + 0.1*noise ; top-2 ; sparse softmax.
// x[B=8,S=4096,D=768] f32, W[E=8,D=768] f32, b[8] f32, noise[B,S,8] f32.
//
// R9: R7's cp.async ring, tuned for 4 CTAs/SM: NSTAGE=2 (56KB smem/CTA),
// 64-reg cap via __launch_bounds__(256,4), x readback split into two
// token-halves to shrink live registers. 32 warps/SM for latency hiding.

#define D_DIM        768
#define E_DIM        8
#define TOK_PER_WARP 4
#define WARPS        8
#define BLOCK        (WARPS * 32)
#define TOK_PER_BLK  (WARPS * TOK_PER_WARP)   // 32
#define D4           (D_DIM / 4)              // 192
#define NCHUNK       (D4 / 32)                // 6
#define NSTAGE       2
#define SW_F4        (E_DIM * D4)             // 1536 float4 = 24 KB
#define SX_WARP_F4   (NSTAGE * TOK_PER_WARP * 32)   // 256 float4 = 4 KB/warp
#define SMEM_BYTES   ((SW_F4 + WARPS * SX_WARP_F4) * 16)  // 57344
#define NOISE_STD    0.1f

#define CP_ASYNC16(dst32, src) \
    asm volatile("cp.async.cg.shared.global [%0], [%1], 16;" \
                 :: "r"(dst32), "l"(src) : "memory")
#define CP_COMMIT() asm volatile("cp.async.commit_group;" ::: "memory")
#define CP_WAIT(n)  asm volatile("cp.async.wait_group %0;" :: "n"(n) : "memory")

__global__ __launch_bounds__(BLOCK, 4)
void router_kernel(const float* __restrict__ x,
                   const float* __restrict__ W,
                   const float* __restrict__ b,
                   const float* __restrict__ noise,
                   float* __restrict__ out,
                   int nTokens, int writeIdx)
{
    extern __shared__ float4 smem[];
    float4* sW4 = smem;                 // [E_DIM * D4]  (16B lane stride: conflict-free)
    float4* sX  = smem + SW_F4;         // ring [WARPS][NSTAGE][TOK*32]

    const int tid  = threadIdx.x;
    const int lane = tid & 31;
    const int wid  = tid >> 5;

    // Stage W into shared once (coalesced float4 copy of contiguous 24 KB)
    {
        const float4* Wg = reinterpret_cast<const float4*>(W);
        #pragma unroll
        for (int i = 0; i < SW_F4 / BLOCK; i++)
            sW4[i * BLOCK + tid] = Wg[i * BLOCK + tid];
    }
    __syncthreads();

    const int tokBase = blockIdx.x * TOK_PER_BLK + wid * TOK_PER_WARP;
    if (tokBase >= nTokens) return;

    const float4* x4 = reinterpret_cast<const float4*>(x) + (size_t)tokBase * D4;

    float4* myX = sX + wid * SX_WARP_F4;
    const unsigned myX32 = (unsigned)__cvta_generic_to_shared(myX);

    float acc[TOK_PER_WARP * E_DIM];
    #pragma unroll
    for (int v = 0; v < TOK_PER_WARP * E_DIM; v++) acc[v] = 0.0f;

    // issue chunk c into ring stage s: 4x cp.async(16B) per lane, one group
    auto issue = [&](int c, int s) {
        #pragma unroll
        for (int t = 0; t < TOK_PER_WARP; t++)
            CP_ASYNC16(myX32 + (unsigned)(((s * TOK_PER_WARP + t) * 32 + lane) * 16),
                       x4 + (size_t)t * D4 + c * 32 + lane);
        CP_COMMIT();
    };

    // compute chunk c from stage s, tokens [t0, t0+2): small live set (8 xv regs)
    auto computeHalf = [&](int c, int s, int t0) {
        float4 xv[2];
        #pragma unroll
        for (int u = 0; u < 2; u++)
            xv[u] = myX[(s * TOK_PER_WARP + t0 + u) * 32 + lane];
        const int p = c * 32 + lane;
        #pragma unroll
        for (int e = 0; e < E_DIM; e++) {
            const float4 wv = sW4[e * D4 + p];       // LDS.128, conflict-free
            #pragma unroll
            for (int u = 0; u < 2; u++)
                acc[(t0 + u) * E_DIM + e] += xv[u].x * wv.x + xv[u].y * wv.y
                                           + xv[u].z * wv.z + xv[u].w * wv.w;
        }
    };
    auto compute = [&](int c, int s) { computeHalf(c, s, 0); computeHalf(c, s, 2); };

    // 2-stage pipeline over 6 chunks (2 committed groups always in flight)
    issue(0, 0); issue(1, 1);
    CP_WAIT(1); compute(0, 0); issue(2, 0);
    CP_WAIT(1); compute(1, 1); issue(3, 1);
    CP_WAIT(1); compute(2, 0); issue(4, 0);
    CP_WAIT(1); compute(3, 1); issue(5, 1);
    CP_WAIT(1); compute(4, 0);
    CP_WAIT(0); compute(5, 1);

    // Log-halving butterfly: after 5 steps lane l holds the complete 32-lane
    // sum for value index v == l  (v = t*8 + e).
    #pragma unroll
    for (int m = 16; m >= 1; m >>= 1) {
        const bool upper = (lane & m) != 0;
        #pragma unroll
        for (int i = 0; i < m; i++) {
            const float lo = acc[i], hi = acc[i + m];
            const float send = upper ? lo : hi;
            const float recv = __shfl_xor_sync(0xFFFFFFFFu, send, m);
            acc[i] = upper ? (hi + recv) : (lo + recv);
        }
    }
    const float sum = acc[0];

    const int t = lane >> 3;            // token within warp
    const int e = lane & 7;             // expert
    const long tok = (long)tokBase + t;

    const float logit = sum + __ldg(b + e)
                      + NOISE_STD * __ldg(noise + (size_t)tokBase * E_DIM + lane);

    // top-1 over the 8-lane expert group (ties -> lower index, jax top_k order)
    float v1 = logit; int i1 = e;
    #pragma unroll
    for (int off = 1; off < 8; off <<= 1) {
        const float ov = __shfl_xor_sync(0xFFFFFFFFu, v1, off);
        const int   oi = __shfl_xor_sync(0xFFFFFFFFu, i1, off);
        if (ov > v1 || (ov == v1 && oi < i1)) { v1 = ov; i1 = oi; }
    }
    // top-2: exclude winner, reduce again
    float v2 = (e == i1) ? -INFINITY : logit; int i2 = e;
    #pragma unroll
    for (int off = 1; off < 8; off <<= 1) {
        const float ov = __shfl_xor_sync(0xFFFFFFFFu, v2, off);
        const int   oi = __shfl_xor_sync(0xFFFFFFFFu, i2, off);
        if (ov > v2 || (ov == v2 && oi < i2)) { v2 = ov; i2 = oi; }
    }

    // 2-element softmax: p1 = 1/(1+exp(v2-v1)), p2 = exp(v2-v1)*p1  (arg <= 0)
    const float ed  = __expf(v2 - v1);
    const float inv = 1.0f / (1.0f + ed);
    const float p   = (e == i1) ? inv : ((e == i2) ? ed * inv : 0.0f);

    out[(size_t)tokBase * E_DIM + lane] = p;   // coalesced 128B per warp

    if (writeIdx && e == 0) {
        float* idxOut = out + (size_t)nTokens * E_DIM;
        idxOut[tok * 2 + 0] = (float)i1;
        idxOut[tok * 2 + 1] = (float)i2;
    }
}

extern "C" void kernel_launch(void* const* d_in, const int* in_sizes, int n_in,
                              void* d_out, int out_size)
{
    const float* x     = (const float*)d_in[0];
    const float* W     = (const float*)d_in[1];
    const float* b     = (const float*)d_in[2];
    const float* noise = (const float*)d_in[3];
    float* out = (float*)d_out;

    const int nTokens = in_sizes[3] / E_DIM;          // B*S from noise elem count
    const int writeIdx = (out_size >= nTokens * E_DIM + nTokens * 2) ? 1 : 0;

    // >48KB dynamic smem opt-in (unconditional; idempotent; capture-safe)
    cudaFuncSetAttribute(router_kernel,
                         cudaFuncAttributeMaxDynamicSharedMemorySize,
                         SMEM_BYTES);

    const int grid = (nTokens + TOK_PER_BLK - 1) / TOK_PER_BLK;
    router_kernel<<<grid, BLOCK, SMEM_BYTES>>>(x, W, b, noise, out, nTokens, writeIdx);
}

// round 11
// speedup vs baseline: 1.6215x; 1.6215x over previous
#include <cuda_runtime.h>
#include <cuda_bf16.h>
#include <math.h>

// DynamicRouter: logits = x @ W^T + b + 0.1*noise ; top-2 ; sparse softmax.
// x[B=8,S=4096,D=768] f32, W[E=8,D=768] f32, b[8] f32, noise[B,S,8] f32.
//
// R11 (= R10 resubmit after infra flake): register double-buffer +
// prefetch.global.L2 two chunks ahead. Prefetch warms L2 ~600cy before the
// LDG, so the LDG is an L2 hit (~250cy) -- shorter than the ~300cy compute
// tail -> scoreboard waits vanish. No smem ring, no readback LDS, no waits.

#define D_DIM        768
#define E_DIM        8
#define TOK_PER_WARP 4
#define WARPS        8
#define BLOCK        (WARPS * 32)
#define TOK_PER_BLK  (WARPS * TOK_PER_WARP)   // 32
#define D4           (D_DIM / 4)              // 192
#define NCHUNK       (D4 / 32)                // 6
#define NOISE_STD    0.1f

#define PREFETCH_L2(addr) \
    asm volatile("prefetch.global.L2 [%0];" :: "l"(addr))

__global__ __launch_bounds__(BLOCK, 3)
void router_kernel(const float* __restrict__ x,
                   const float* __restrict__ W,
                   const float* __restrict__ b,
                   const float* __restrict__ noise,
                   float* __restrict__ out,
                   int nTokens, int writeIdx)
{
    __shared__ float4 sW4[E_DIM * D4];   // 24 KB, 16B lane stride: conflict-free

    const int tid  = threadIdx.x;
    const int lane = tid & 31;
    const int wid  = tid >> 5;

    // Stage W into shared once (coalesced float4 copy of contiguous 24 KB)
    {
        const float4* Wg = reinterpret_cast<const float4*>(W);
        #pragma unroll
        for (int i = 0; i < (E_DIM * D4) / BLOCK; i++)
            sW4[i * BLOCK + tid] = Wg[i * BLOCK + tid];
    }
    __syncthreads();

    const int tokBase = blockIdx.x * TOK_PER_BLK + wid * TOK_PER_WARP;
    if (tokBase >= nTokens) return;

    const float4* x4 = reinterpret_cast<const float4*>(x) + (size_t)tokBase * D4;

    // L2 prefetch of one whole 2KB chunk with one warp-instruction:
    // lanes 0..15 each touch one distinct 128B line (4 tokens x 4 lines/chunk).
    auto pf = [&](int c) {
        if (lane < 16) {
            const float4* a = x4 + (size_t)(lane >> 2) * D4 + c * 32 + (lane & 3) * 8;
            PREFETCH_L2(a);
        }
    };

    auto loadChunk = [&](float4* buf, int c) {
        #pragma unroll
        for (int t = 0; t < TOK_PER_WARP; t++)
            buf[t] = x4[(size_t)t * D4 + c * 32 + lane];   // coalesced 512B/token
    };

    float acc[TOK_PER_WARP * E_DIM];
    #pragma unroll
    for (int v = 0; v < TOK_PER_WARP * E_DIM; v++) acc[v] = 0.0f;

    auto computeChunk = [&](const float4* buf, int c) {
        const int p = c * 32 + lane;
        #pragma unroll
        for (int e = 0; e < E_DIM; e++) {
            const float4 wv = sW4[e * D4 + p];             // LDS.128, reused x4 tokens
            #pragma unroll
            for (int t = 0; t < TOK_PER_WARP; t++)
                acc[t * E_DIM + e] += buf[t].x * wv.x + buf[t].y * wv.y
                                    + buf[t].z * wv.z + buf[t].w * wv.w;
        }
    };

    // double-buffered, fully unrolled pipeline with 2-chunk-ahead L2 prefetch
    float4 bufA[TOK_PER_WARP], bufB[TOK_PER_WARP];
    loadChunk(bufA, 0);
    pf(1);
    loadChunk(bufB, 1);  pf(2); computeChunk(bufA, 0);
    loadChunk(bufA, 2);  pf(3); computeChunk(bufB, 1);
    loadChunk(bufB, 3);  pf(4); computeChunk(bufA, 2);
    loadChunk(bufA, 4);  pf(5); computeChunk(bufB, 3);
    loadChunk(bufB, 5);          computeChunk(bufA, 4);
                                 computeChunk(bufB, 5);

    // Log-halving butterfly: after 5 steps lane l holds the complete 32-lane
    // sum for value index v == l  (v = t*8 + e).
    #pragma unroll
    for (int m = 16; m >= 1; m >>= 1) {
        const bool upper = (lane & m) != 0;
        #pragma unroll
        for (int i = 0; i < m; i++) {
            const float lo = acc[i], hi = acc[i + m];
            const float send = upper ? lo : hi;
            const float recv = __shfl_xor_sync(0xFFFFFFFFu, send, m);
            acc[i] = upper ? (hi + recv) : (lo + recv);
        }
    }
    const float sum = acc[0];

    const int t = lane >> 3;            // token within warp
    const int e = lane & 7;             // expert
    const long tok = (long)tokBase + t;

    const float logit = sum + __ldg(b + e)
                      + NOISE_STD * __ldg(noise + (size_t)tokBase * E_DIM + lane);

    // top-1 over the 8-lane expert group (ties -> lower index, jax top_k order)
    float v1 = logit; int i1 = e;
    #pragma unroll
    for (int off = 1; off < 8; off <<= 1) {
        const float ov = __shfl_xor_sync(0xFFFFFFFFu, v1, off);
        const int   oi = __shfl_xor_sync(0xFFFFFFFFu, i1, off);
        if (ov > v1 || (ov == v1 && oi < i1)) { v1 = ov; i1 = oi; }
    }
    // top-2: exclude winner, reduce again
    float v2 = (e == i1) ? -INFINITY : logit; int i2 = e;
    #pragma unroll
    for (int off = 1; off < 8; off <<= 1) {
        const float ov = __shfl_xor_sync(0xFFFFFFFFu, v2, off);
        const int   oi = __shfl_xor_sync(0xFFFFFFFFu, i2, off);
        if (ov > v2 || (ov == v2 && oi < i2)) { v2 = ov; i2 = oi; }
    }

    // 2-element softmax: p1 = 1/(1+exp(v2-v1)), p2 = exp(v2-v1)*p1  (arg <= 0)
    const float ed  = __expf(v2 - v1);
    const float inv = 1.0f / (1.0f + ed);
    const float p   = (e == i1) ? inv : ((e == i2) ? ed * inv : 0.0f);

    out[(size_t)tokBase * E_DIM + lane] = p;   // coalesced 128B per warp

    if (writeIdx && e == 0) {
        float* idxOut = out + (size_t)nTokens * E_DIM;
        idxOut[tok * 2 + 0] = (float)i1;
        idxOut[tok * 2 + 1] = (float)i2;
    }
}

extern "C" void kernel_launch(void* const* d_in, const int* in_sizes, int n_in,
                              void* d_out, int out_size)
{
    const float* x     = (const float*)d_in[0];
    const float* W     = (const float*)d_in[1];
    const float* b     = (const float*)d_in[2];
    const float* noise = (const float*)d_in[3];
    float* out = (float*)d_out;

    const int nTokens = in_sizes[3] / E_DIM;          // B*S from noise elem count
    const int writeIdx = (out_size >= nTokens * E_DIM + nTokens * 2) ? 1 : 0;

    const int grid = (nTokens + TOK_PER_BLK - 1) / TOK_PER_BLK;
    router_kernel<<<grid, BLOCK>>>(x, W, b, noise, out, nTokens, writeIdx);
}